// round 9
// baseline (speedup 1.0000x reference)
#include <cuda_runtime.h>
#include <cuda_bf16.h>
#include <cstdint>
#include <math.h>

typedef unsigned int u32;

// ---------------- problem constants ----------------
#define T_TOK   2048
#define HID     4096
#define NH      32
#define NKH     8
#define HD      128
#define VDIM    64
#define QKV_N   (NH*HD + NKH*HD + NKH*VDIM)   // 5632
#define K_OFF   (NH*HD)                        // 4096
#define V_OFF   (NH*HD + NKH*HD)               // 5120
#define WINDOW_SZ 1024
#define SCALE_ATTN 0.08838834764831845f        // 128^-0.5
#define V_SCALE_C  1.25f

// ---------------- scratch (no allocs allowed) ----------------
__device__ float g_qkv [T_TOK * QKV_N];
__device__ float g_attn[T_TOK * NH * VDIM];

// =====================================================================
// mma helpers
// =====================================================================
__device__ __forceinline__ u32 f2tf32(float f) {
    u32 r;
    asm("cvt.rna.tf32.f32 %0, %1;" : "=r"(r) : "f"(f));
    return r;
}

__device__ __forceinline__ void mma_tf32(float c[4], const u32 a[4],
                                         const u32 b[2]) {
    asm volatile(
        "mma.sync.aligned.m16n8k8.row.col.f32.tf32.tf32.f32 "
        "{%0,%1,%2,%3}, {%4,%5,%6,%7}, {%8,%9}, {%0,%1,%2,%3};\n"
        : "+f"(c[0]), "+f"(c[1]), "+f"(c[2]), "+f"(c[3])
        : "r"(a[0]), "r"(a[1]), "r"(a[2]), "r"(a[3]), "r"(b[0]), "r"(b[1]));
}

__device__ __forceinline__ void mma_bf16(float c[4], const u32 a[4],
                                         const u32 b[2]) {
    asm volatile(
        "mma.sync.aligned.m16n8k16.row.col.f32.bf16.bf16.f32 "
        "{%0,%1,%2,%3}, {%4,%5,%6,%7}, {%8,%9}, {%0,%1,%2,%3};\n"
        : "+f"(c[0]), "+f"(c[1]), "+f"(c[2]), "+f"(c[3])
        : "r"(a[0]), "r"(a[1]), "r"(a[2]), "r"(a[3]), "r"(b[0]), "r"(b[1]));
}

// split two floats into packed bf16 hi-pair and lo-pair.
// hi = top-16-bit truncation of f; lo = bf16(f - hi).  x -> low bf16 lane.
__device__ __forceinline__ void split2(float x, float y, u32& hi, u32& lo) {
    u32 bx = __float_as_uint(x), by = __float_as_uint(y);
    hi = __byte_perm(bx, by, 0x7632);
    float lx = x - __uint_as_float(bx & 0xffff0000u);
    float ly = y - __uint_as_float(by & 0xffff0000u);
    lo = __byte_perm(__float_as_uint(lx), __float_as_uint(ly), 0x7632);
}

// =====================================================================
// TF32 tensor-core GEMM (unchanged, known-good).
// =====================================================================
#define GBM 128
#define GBN 128
#define GBK 32
#define AS_STRIDE 36
#define BS_STRIDE 132
#define AS_ELEMS (GBM*AS_STRIDE)
#define BS_ELEMS (GBK*BS_STRIDE)
#define GEMM_SMEM ((2*AS_ELEMS + 2*BS_ELEMS) * 4)

__global__ __launch_bounds__(256, 2) void gemm_tf32_kernel(
    const float* __restrict__ A, const float* __restrict__ B,
    float* __restrict__ C, int M, int N, int K)
{
    extern __shared__ u32 smem_u[];
    u32* As = smem_u;
    u32* Bs = smem_u + 2 * AS_ELEMS;

    const int tid  = threadIdx.x;
    const int warp = tid >> 5;
    const int lane = tid & 31;
    const int wr = warp >> 2;
    const int wc = warp & 3;
    const int g  = lane >> 2;
    const int tg = lane & 3;

    const int bx = blockIdx.x, by = blockIdx.y;
    const float* Ab = A + (size_t)by * GBM * K;
    const float* Bb = B + (size_t)bx * GBN;

    const int arow0 = tid >> 3;
    const int acol  = (tid & 7) * 4;
    const int brow0 = tid >> 5;
    const int bcol  = (tid & 31) * 4;

    float acc[4][4][4];
    #pragma unroll
    for (int i = 0; i < 4; i++)
        #pragma unroll
        for (int j = 0; j < 4; j++)
            #pragma unroll
            for (int r = 0; r < 4; r++) acc[i][j][r] = 0.f;

    const int nc = K / GBK;

    #pragma unroll
    for (int p = 0; p < 4; p++) {
        int r = arow0 + p * 32;
        float4 v = *(const float4*)(Ab + (size_t)r * K + acol);
        u32* d = &As[r * AS_STRIDE + acol];
        d[0] = f2tf32(v.x); d[1] = f2tf32(v.y); d[2] = f2tf32(v.z); d[3] = f2tf32(v.w);
    }
    #pragma unroll
    for (int p = 0; p < 4; p++) {
        int r = brow0 + p * 8;
        float4 v = *(const float4*)(Bb + (size_t)r * N + bcol);
        u32* d = &Bs[r * BS_STRIDE + bcol];
        d[0] = f2tf32(v.x); d[1] = f2tf32(v.y); d[2] = f2tf32(v.z); d[3] = f2tf32(v.w);
    }
    __syncthreads();

    int pb = 0;
    for (int c = 0; c < nc; c++) {
        float4 stA[4], stB[4];
        const bool has_next = (c + 1 < nc);
        if (has_next) {
            int k0 = (c + 1) * GBK;
            #pragma unroll
            for (int p = 0; p < 4; p++)
                stA[p] = *(const float4*)(Ab + (size_t)(arow0 + p*32) * K + k0 + acol);
            #pragma unroll
            for (int p = 0; p < 4; p++)
                stB[p] = *(const float4*)(Bb + (size_t)(k0 + brow0 + p*8) * N + bcol);
        }

        const u32* Ac = As + pb * AS_ELEMS;
        const u32* Bc = Bs + pb * BS_ELEMS;

        #pragma unroll
        for (int ks = 0; ks < 4; ks++) {
            u32 af[4][4], bf[4][2];
            #pragma unroll
            for (int mt = 0; mt < 4; mt++) {
                int base = (wr*64 + mt*16 + g) * AS_STRIDE + ks*8 + tg;
                af[mt][0] = Ac[base];
                af[mt][1] = Ac[base + 8*AS_STRIDE];
                af[mt][2] = Ac[base + 4];
                af[mt][3] = Ac[base + 8*AS_STRIDE + 4];
            }
            #pragma unroll
            for (int nt = 0; nt < 4; nt++) {
                int col = wc*32 + nt*8 + g;
                int idx = (ks*8 + tg) * BS_STRIDE + col;
                bf[nt][0] = Bc[idx];
                bf[nt][1] = Bc[idx + 4*BS_STRIDE];
            }
            #pragma unroll
            for (int mt = 0; mt < 4; mt++)
                #pragma unroll
                for (int nt = 0; nt < 4; nt++)
                    mma_tf32(acc[mt][nt], af[mt], bf[nt]);
        }

        if (has_next) {
            u32* An = As + (1 - pb) * AS_ELEMS;
            u32* Bn = Bs + (1 - pb) * BS_ELEMS;
            #pragma unroll
            for (int p = 0; p < 4; p++) {
                u32* d = &An[(arow0 + p*32) * AS_STRIDE + acol];
                d[0]=f2tf32(stA[p].x); d[1]=f2tf32(stA[p].y);
                d[2]=f2tf32(stA[p].z); d[3]=f2tf32(stA[p].w);
            }
            #pragma unroll
            for (int p = 0; p < 4; p++) {
                u32* d = &Bn[(brow0 + p*8) * BS_STRIDE + bcol];
                d[0]=f2tf32(stB[p].x); d[1]=f2tf32(stB[p].y);
                d[2]=f2tf32(stB[p].z); d[3]=f2tf32(stB[p].w);
            }
            __syncthreads();
            pb ^= 1;
        }
    }

    float* Cb = C + (size_t)by * GBM * N + (size_t)bx * GBN;
    #pragma unroll
    for (int mt = 0; mt < 4; mt++) {
        int row = wr*64 + mt*16 + g;
        #pragma unroll
        for (int nt = 0; nt < 4; nt++) {
            int col = wc*32 + nt*8 + tg*2;
            *(float2*)(Cb + (size_t)row * N + col) =
                make_float2(acc[mt][nt][0], acc[mt][nt][1]);
            *(float2*)(Cb + (size_t)(row + 8) * N + col) =
                make_float2(acc[mt][nt][2], acc[mt][nt][3]);
        }
    }
}

// =====================================================================
// RoPE + V scale (sincos computed once per token).
// =====================================================================
__global__ __launch_bounds__(256) void rope_kernel(
    float* __restrict__ qkv, const int* __restrict__ positions)
{
    __shared__ float cs[64], sn[64];
    const int t = blockIdx.x;
    const int tid = threadIdx.x;
    float* row = qkv + (size_t)t * QKV_N;

    if (tid < 64) {
        float pos = (float)positions[t];
        float inv = powf(1.0e6f, -(float)tid * (1.0f / 64.0f));
        float fr = pos * inv;
        float s, c;
        sincosf(fr, &s, &c);
        cs[tid] = c; sn[tid] = s;
    }
    __syncthreads();

    for (int idx = tid; idx < 40 * 64; idx += 256) {
        int head = idx >> 6;
        int i = idx & 63;
        int base = (head < NH) ? head * HD : K_OFF + (head - NH) * HD;
        float c = cs[i], s = sn[i];
        float x1 = row[base + i];
        float x2 = row[base + i + 64];
        row[base + i]      = x1 * c - x2 * s;
        row[base + i + 64] = x2 * c + x1 * s;
    }
    for (int idx = tid; idx < NKH * VDIM; idx += 256) {
        row[V_OFF + idx] *= V_SCALE_C;
    }
}

// =====================================================================
// Flash attention, all-register P, split-bf16 everywhere.
//   S  = QK^T : 3-pass split-bf16, K hi/lo interleaved in smem (LDS.64)
//   PV        : 3-pass split-bf16, P packed from S C-frags in registers,
//               V pre-split hi/lo in transposed key-pair layout.
// Block = (head, 64 q rows), 4 warps x 16 rows, 3 blocks/SM.
// =====================================================================
#define A_BM 64
#define KP2_STRIDE 136     // u32; hi/lo interleaved pairs, 68 pair-slots
#define VT_STRIDE  72      // u32; (8tg+g) distinct banks for frag loads
#define ATTN_SMEM ((64*KP2_STRIDE + 2*32*VT_STRIDE) * 4)   // 52 KB

__global__ __launch_bounds__(128, 3) void attn_kernel(
    const float* __restrict__ qkv, const float* __restrict__ sink,
    float* __restrict__ out)
{
    extern __shared__ u32 smem_a[];
    u32* KP   = smem_a;                      // [64 key][68 pair][2] (hi,lo)
    u32* VThi = KP + 64 * KP2_STRIDE;        // [32 keypair][72] (n fast)
    u32* VTlo = VThi + 32 * VT_STRIDE;

    const int h  = blockIdx.y;
    const int m0 = blockIdx.x * A_BM;
    const int kh = h >> 2;

    const int tid  = threadIdx.x;
    const int warp = tid >> 5;
    const int lane = tid & 31;
    const int g  = lane >> 2;
    const int tg = lane & 3;
    const int wm = warp * 16;

    const float* Kg = qkv + K_OFF + (size_t)kh * HD;
    const float* Vg = qkv + V_OFF + (size_t)kh * VDIM;

    // ---- Q fragments -> registers (split bf16 hi/lo), once per block ----
    u32 qhi[8][4], qlo[8][4];
    {
        const float* Qr0 = qkv + (size_t)(m0 + wm + g) * QKV_N + h * HD;
        const float* Qr1 = Qr0 + 8 * (size_t)QKV_N;
        #pragma unroll
        for (int ks = 0; ks < 8; ks++) {
            int c0 = ks * 16 + 2 * tg;
            float2 x0 = *(const float2*)(Qr0 + c0);
            float2 x1 = *(const float2*)(Qr1 + c0);
            float2 x2 = *(const float2*)(Qr0 + c0 + 8);
            float2 x3 = *(const float2*)(Qr1 + c0 + 8);
            split2(x0.x, x0.y, qhi[ks][0], qlo[ks][0]);
            split2(x1.x, x1.y, qhi[ks][1], qlo[ks][1]);
            split2(x2.x, x2.y, qhi[ks][2], qlo[ks][2]);
            split2(x3.x, x3.y, qhi[ks][3], qlo[ks][3]);
        }
    }

    const float snk = sink[h];
    float m_r[2] = {snk, snk};
    float l_r[2] = {1.0f, 1.0f};
    float O[8][4];
    #pragma unroll
    for (int nt = 0; nt < 8; nt++)
        #pragma unroll
        for (int r = 0; r < 4; r++) O[nt][r] = 0.f;

    const int gi0 = m0 + wm + g;
    const int gi1 = gi0 + 8;

    int n0s = m0 - WINDOW_SZ;
    if (n0s < 0) n0s = 0;

    for (int n0 = n0s; n0 <= m0; n0 += 64) {
        __syncthreads();   // previous tile fully consumed

        // ---- K tile: split + interleave (hi,lo) pairs ----
        for (int idx = tid; idx < 64 * 32; idx += 128) {
            int r = idx >> 5, c4 = (idx & 31) * 4;    // c4 = float col
            float4 v = *(const float4*)(Kg + (size_t)(n0 + r) * QKV_N + c4);
            u32 h01, l01, h23, l23;
            split2(v.x, v.y, h01, l01);
            split2(v.z, v.w, h23, l23);
            // u32 slot = r*136 + c4 (pair index c4/2, interleave factor 2)
            *(uint4*)&KP[r * KP2_STRIDE + c4] = make_uint4(h01, l01, h23, l23);
        }
        // ---- V tile: transpose to key-pair layout, split hi/lo ----
        for (int i = tid; i < 64 * 32; i += 128) {
            int n = i & 63, kp = i >> 6;
            float a = Vg[(size_t)(n0 + 2*kp)     * QKV_N + n];
            float b = Vg[(size_t)(n0 + 2*kp + 1) * QKV_N + n];
            u32 hi, lo;
            split2(a, b, hi, lo);
            VThi[kp * VT_STRIDE + n] = hi;
            VTlo[kp * VT_STRIDE + n] = lo;
        }
        __syncthreads();

        // ---- S = Q K^T (hi*hi + lo*hi + hi*lo) ----
        float Sa[8][4];
        #pragma unroll
        for (int nt = 0; nt < 8; nt++)
            #pragma unroll
            for (int r = 0; r < 4; r++) Sa[nt][r] = 0.f;

        #pragma unroll
        for (int ks = 0; ks < 8; ks++) {
            #pragma unroll
            for (int nt = 0; nt < 8; nt++) {
                int base = (nt*8 + g) * KP2_STRIDE + 2*(ks*8 + tg);
                uint2 b0 = *(const uint2*)&KP[base];
                uint2 b1 = *(const uint2*)&KP[base + 8];
                u32 bh[2] = {b0.x, b1.x};
                u32 bl[2] = {b0.y, b1.y};
                mma_bf16(Sa[nt], qhi[ks], bh);
                mma_bf16(Sa[nt], qlo[ks], bh);
                mma_bf16(Sa[nt], qhi[ks], bl);
            }
        }

        // ---- scale + mask ----
        #pragma unroll
        for (int nt = 0; nt < 8; nt++) {
            #pragma unroll
            for (int cc = 0; cc < 2; cc++) {
                int gj = n0 + nt*8 + 2*tg + cc;
                bool v0 = (gj <= gi0) && (gj + WINDOW_SZ > gi0);
                bool v1 = (gj <= gi1) && (gj + WINDOW_SZ > gi1);
                Sa[nt][cc]     = v0 ? Sa[nt][cc]     * SCALE_ATTN : -1.0e30f;
                Sa[nt][2 + cc] = v1 ? Sa[nt][2 + cc] * SCALE_ATTN : -1.0e30f;
            }
        }

        // ---- online softmax ----
        float tm0 = -1.0e30f, tm1 = -1.0e30f;
        #pragma unroll
        for (int nt = 0; nt < 8; nt++) {
            tm0 = fmaxf(tm0, fmaxf(Sa[nt][0], Sa[nt][1]));
            tm1 = fmaxf(tm1, fmaxf(Sa[nt][2], Sa[nt][3]));
        }
        tm0 = fmaxf(tm0, __shfl_xor_sync(0xffffffffu, tm0, 1));
        tm0 = fmaxf(tm0, __shfl_xor_sync(0xffffffffu, tm0, 2));
        tm1 = fmaxf(tm1, __shfl_xor_sync(0xffffffffu, tm1, 1));
        tm1 = fmaxf(tm1, __shfl_xor_sync(0xffffffffu, tm1, 2));

        float mn0 = fmaxf(m_r[0], tm0);
        float mn1 = fmaxf(m_r[1], tm1);
        float corr0 = __expf(m_r[0] - mn0);
        float corr1 = __expf(m_r[1] - mn1);
        m_r[0] = mn0; m_r[1] = mn1;

        float rs0 = 0.f, rs1 = 0.f;
        #pragma unroll
        for (int nt = 0; nt < 8; nt++) {
            #pragma unroll
            for (int cc = 0; cc < 2; cc++) {
                float p0 = __expf(Sa[nt][cc]     - mn0);
                float p1 = __expf(Sa[nt][2 + cc] - mn1);
                Sa[nt][cc]     = p0;
                Sa[nt][2 + cc] = p1;
                rs0 += p0; rs1 += p1;
            }
        }
        rs0 += __shfl_xor_sync(0xffffffffu, rs0, 1);
        rs0 += __shfl_xor_sync(0xffffffffu, rs0, 2);
        rs1 += __shfl_xor_sync(0xffffffffu, rs1, 1);
        rs1 += __shfl_xor_sync(0xffffffffu, rs1, 2);

        l_r[0] = l_r[0] * corr0 + rs0;
        l_r[1] = l_r[1] * corr1 + rs1;
        #pragma unroll
        for (int nt = 0; nt < 8; nt++) {
            O[nt][0] *= corr0; O[nt][1] *= corr0;
            O[nt][2] *= corr1; O[nt][3] *= corr1;
        }

        // ---- O += P V : P packed from registers, V split in smem ----
        #pragma unroll
        for (int kq = 0; kq < 4; kq++) {
            u32 phi[4], plo[4];
            split2(Sa[2*kq][0],   Sa[2*kq][1],   phi[0], plo[0]);
            split2(Sa[2*kq][2],   Sa[2*kq][3],   phi[1], plo[1]);
            split2(Sa[2*kq+1][0], Sa[2*kq+1][1], phi[2], plo[2]);
            split2(Sa[2*kq+1][2], Sa[2*kq+1][3], phi[3], plo[3]);
            #pragma unroll
            for (int nt = 0; nt < 8; nt++) {
                int i0 = (kq*8 + tg) * VT_STRIDE + nt*8 + g;
                u32 vh[2], vl[2];
                vh[0] = VThi[i0];                 vl[0] = VTlo[i0];
                vh[1] = VThi[i0 + 4*VT_STRIDE];   vl[1] = VTlo[i0 + 4*VT_STRIDE];
                mma_bf16(O[nt], phi, vh);
                mma_bf16(O[nt], plo, vh);
                mma_bf16(O[nt], phi, vl);
            }
        }
    }

    // ---- epilogue ----
    float inv0 = 1.0f / l_r[0];
    float inv1 = 1.0f / l_r[1];
    #pragma unroll
    for (int nt = 0; nt < 8; nt++) {
        int col = h * VDIM + nt*8 + 2*tg;
        *(float2*)(out + (size_t)gi0 * (NH * VDIM) + col) =
            make_float2(O[nt][0] * inv0, O[nt][1] * inv0);
        *(float2*)(out + (size_t)gi1 * (NH * VDIM) + col) =
            make_float2(O[nt][2] * inv1, O[nt][3] * inv1);
    }
}

// =====================================================================
// launch
// =====================================================================
extern "C" void kernel_launch(void* const* d_in, const int* in_sizes, int n_in,
                              void* d_out, int out_size)
{
    const int*   positions = (const int*)  d_in[0];
    const float* hidden    = (const float*)d_in[1];
    const float* Wqkv      = (const float*)d_in[2];
    const float* Wo        = (const float*)d_in[3];
    const float* sink      = (const float*)d_in[4];
    float* out = (float*)d_out;

    float *qkv, *attn;
    cudaGetSymbolAddress((void**)&qkv,  g_qkv);
    cudaGetSymbolAddress((void**)&attn, g_attn);

    cudaFuncSetAttribute(gemm_tf32_kernel,
                         cudaFuncAttributeMaxDynamicSharedMemorySize, GEMM_SMEM);
    cudaFuncSetAttribute(attn_kernel,
                         cudaFuncAttributeMaxDynamicSharedMemorySize, ATTN_SMEM);

    // 1) QKV projection (tf32 tensor cores)
    {
        dim3 grid(QKV_N / GBN, T_TOK / GBM);
        gemm_tf32_kernel<<<grid, 256, GEMM_SMEM>>>(hidden, Wqkv, qkv,
                                                   T_TOK, QKV_N, HID);
    }
    // 2) RoPE + V scale
    rope_kernel<<<T_TOK, 256>>>(qkv, positions);
    // 3) attention (split-bf16 S and PV, register-resident P)
    {
        dim3 grid(T_TOK / A_BM, NH);
        attn_kernel<<<grid, 128, ATTN_SMEM>>>(qkv, sink, attn);
    }
    // 4) output projection (tf32 tensor cores)
    {
        dim3 grid(HID / GBN, T_TOK / GBM);
        gemm_tf32_kernel<<<grid, 256, GEMM_SMEM>>>(attn, Wo, out,
                                                   T_TOK, HID, NH * VDIM);
    }
}

// round 10
// speedup vs baseline: 1.0188x; 1.0188x over previous
#include <cuda_runtime.h>
#include <cuda_bf16.h>
#include <cstdint>
#include <math.h>

typedef unsigned int u32;

// ---------------- problem constants ----------------
#define T_TOK   2048
#define HID     4096
#define NH      32
#define NKH     8
#define HD      128
#define VDIM    64
#define QKV_N   (NH*HD + NKH*HD + NKH*VDIM)   // 5632
#define K_OFF   (NH*HD)                        // 4096
#define V_OFF   (NH*HD + NKH*HD)               // 5120
#define WINDOW_SZ 1024
#define SCALE_ATTN 0.08838834764831845f        // 128^-0.5
#define V_SCALE_C  1.25f

// ---------------- scratch (no allocs allowed) ----------------
__device__ float g_qkv [T_TOK * QKV_N];
__device__ float g_attn[T_TOK * NH * VDIM];
// prepacked K: [kh][key][32 uint4]  (row = 64 pairs, interleaved hi,lo)
__device__ uint4 g_kp[NKH * T_TOK * 32];            // 8 MB
// prepacked V: [kh][keypair][2 (hi,lo)][16 uint4]   (row = 64 n-values)
__device__ uint4 g_vt[NKH * (T_TOK/2) * 2 * 16];    // 4 MB

// =====================================================================
// helpers
// =====================================================================
__device__ __forceinline__ u32 f2tf32(float f) {
    u32 r;
    asm("cvt.rna.tf32.f32 %0, %1;" : "=r"(r) : "f"(f));
    return r;
}

__device__ __forceinline__ void mma_tf32(float c[4], const u32 a[4],
                                         const u32 b[2]) {
    asm volatile(
        "mma.sync.aligned.m16n8k8.row.col.f32.tf32.tf32.f32 "
        "{%0,%1,%2,%3}, {%4,%5,%6,%7}, {%8,%9}, {%0,%1,%2,%3};\n"
        : "+f"(c[0]), "+f"(c[1]), "+f"(c[2]), "+f"(c[3])
        : "r"(a[0]), "r"(a[1]), "r"(a[2]), "r"(a[3]), "r"(b[0]), "r"(b[1]));
}

__device__ __forceinline__ void mma_bf16(float c[4], const u32 a[4],
                                         const u32 b[2]) {
    asm volatile(
        "mma.sync.aligned.m16n8k16.row.col.f32.bf16.bf16.f32 "
        "{%0,%1,%2,%3}, {%4,%5,%6,%7}, {%8,%9}, {%0,%1,%2,%3};\n"
        : "+f"(c[0]), "+f"(c[1]), "+f"(c[2]), "+f"(c[3])
        : "r"(a[0]), "r"(a[1]), "r"(a[2]), "r"(a[3]), "r"(b[0]), "r"(b[1]));
}

// split two floats into packed bf16 hi-pair and lo-pair.
__device__ __forceinline__ void split2(float x, float y, u32& hi, u32& lo) {
    u32 bx = __float_as_uint(x), by = __float_as_uint(y);
    hi = __byte_perm(bx, by, 0x7632);
    float lx = x - __uint_as_float(bx & 0xffff0000u);
    float ly = y - __uint_as_float(by & 0xffff0000u);
    lo = __byte_perm(__float_as_uint(lx), __float_as_uint(ly), 0x7632);
}

__device__ __forceinline__ void cp16(void* smem_dst, const void* gmem_src) {
    u32 s = (u32)__cvta_generic_to_shared(smem_dst);
    asm volatile("cp.async.ca.shared.global [%0], [%1], 16;\n"
                 :: "r"(s), "l"(gmem_src));
}
#define CP_COMMIT() asm volatile("cp.async.commit_group;\n" ::: "memory")
#define CP_WAIT(N)  asm volatile("cp.async.wait_group %0;\n" :: "n"(N) : "memory")

// =====================================================================
// TF32 tensor-core GEMM (unchanged, known-good).
// =====================================================================
#define GBM 128
#define GBN 128
#define GBK 32
#define AS_STRIDE 36
#define BS_STRIDE 132
#define AS_ELEMS (GBM*AS_STRIDE)
#define BS_ELEMS (GBK*BS_STRIDE)
#define GEMM_SMEM ((2*AS_ELEMS + 2*BS_ELEMS) * 4)

__global__ __launch_bounds__(256, 2) void gemm_tf32_kernel(
    const float* __restrict__ A, const float* __restrict__ B,
    float* __restrict__ C, int M, int N, int K)
{
    extern __shared__ u32 smem_u[];
    u32* As = smem_u;
    u32* Bs = smem_u + 2 * AS_ELEMS;

    const int tid  = threadIdx.x;
    const int warp = tid >> 5;
    const int lane = tid & 31;
    const int wr = warp >> 2;
    const int wc = warp & 3;
    const int g  = lane >> 2;
    const int tg = lane & 3;

    const int bx = blockIdx.x, by = blockIdx.y;
    const float* Ab = A + (size_t)by * GBM * K;
    const float* Bb = B + (size_t)bx * GBN;

    const int arow0 = tid >> 3;
    const int acol  = (tid & 7) * 4;
    const int brow0 = tid >> 5;
    const int bcol  = (tid & 31) * 4;

    float acc[4][4][4];
    #pragma unroll
    for (int i = 0; i < 4; i++)
        #pragma unroll
        for (int j = 0; j < 4; j++)
            #pragma unroll
            for (int r = 0; r < 4; r++) acc[i][j][r] = 0.f;

    const int nc = K / GBK;

    #pragma unroll
    for (int p = 0; p < 4; p++) {
        int r = arow0 + p * 32;
        float4 v = *(const float4*)(Ab + (size_t)r * K + acol);
        u32* d = &As[r * AS_STRIDE + acol];
        d[0] = f2tf32(v.x); d[1] = f2tf32(v.y); d[2] = f2tf32(v.z); d[3] = f2tf32(v.w);
    }
    #pragma unroll
    for (int p = 0; p < 4; p++) {
        int r = brow0 + p * 8;
        float4 v = *(const float4*)(Bb + (size_t)r * N + bcol);
        u32* d = &Bs[r * BS_STRIDE + bcol];
        d[0] = f2tf32(v.x); d[1] = f2tf32(v.y); d[2] = f2tf32(v.z); d[3] = f2tf32(v.w);
    }
    __syncthreads();

    int pb = 0;
    for (int c = 0; c < nc; c++) {
        float4 stA[4], stB[4];
        const bool has_next = (c + 1 < nc);
        if (has_next) {
            int k0 = (c + 1) * GBK;
            #pragma unroll
            for (int p = 0; p < 4; p++)
                stA[p] = *(const float4*)(Ab + (size_t)(arow0 + p*32) * K + k0 + acol);
            #pragma unroll
            for (int p = 0; p < 4; p++)
                stB[p] = *(const float4*)(Bb + (size_t)(k0 + brow0 + p*8) * N + bcol);
        }

        const u32* Ac = As + pb * AS_ELEMS;
        const u32* Bc = Bs + pb * BS_ELEMS;

        #pragma unroll
        for (int ks = 0; ks < 4; ks++) {
            u32 af[4][4], bf[4][2];
            #pragma unroll
            for (int mt = 0; mt < 4; mt++) {
                int base = (wr*64 + mt*16 + g) * AS_STRIDE + ks*8 + tg;
                af[mt][0] = Ac[base];
                af[mt][1] = Ac[base + 8*AS_STRIDE];
                af[mt][2] = Ac[base + 4];
                af[mt][3] = Ac[base + 8*AS_STRIDE + 4];
            }
            #pragma unroll
            for (int nt = 0; nt < 4; nt++) {
                int col = wc*32 + nt*8 + g;
                int idx = (ks*8 + tg) * BS_STRIDE + col;
                bf[nt][0] = Bc[idx];
                bf[nt][1] = Bc[idx + 4*BS_STRIDE];
            }
            #pragma unroll
            for (int mt = 0; mt < 4; mt++)
                #pragma unroll
                for (int nt = 0; nt < 4; nt++)
                    mma_tf32(acc[mt][nt], af[mt], bf[nt]);
        }

        if (has_next) {
            u32* An = As + (1 - pb) * AS_ELEMS;
            u32* Bn = Bs + (1 - pb) * BS_ELEMS;
            #pragma unroll
            for (int p = 0; p < 4; p++) {
                u32* d = &An[(arow0 + p*32) * AS_STRIDE + acol];
                d[0]=f2tf32(stA[p].x); d[1]=f2tf32(stA[p].y);
                d[2]=f2tf32(stA[p].z); d[3]=f2tf32(stA[p].w);
            }
            #pragma unroll
            for (int p = 0; p < 4; p++) {
                u32* d = &Bn[(brow0 + p*8) * BS_STRIDE + bcol];
                d[0]=f2tf32(stB[p].x); d[1]=f2tf32(stB[p].y);
                d[2]=f2tf32(stB[p].z); d[3]=f2tf32(stB[p].w);
            }
            __syncthreads();
            pb ^= 1;
        }
    }

    float* Cb = C + (size_t)by * GBM * N + (size_t)bx * GBN;
    #pragma unroll
    for (int mt = 0; mt < 4; mt++) {
        int row = wr*64 + mt*16 + g;
        #pragma unroll
        for (int nt = 0; nt < 4; nt++) {
            int col = wc*32 + nt*8 + tg*2;
            *(float2*)(Cb + (size_t)row * N + col) =
                make_float2(acc[mt][nt][0], acc[mt][nt][1]);
            *(float2*)(Cb + (size_t)(row + 8) * N + col) =
                make_float2(acc[mt][nt][2], acc[mt][nt][3]);
        }
    }
}

// =====================================================================
// RoPE + V scale (sincos computed once per token).
// =====================================================================
__global__ __launch_bounds__(256) void rope_kernel(
    float* __restrict__ qkv, const int* __restrict__ positions)
{
    __shared__ float cs[64], sn[64];
    const int t = blockIdx.x;
    const int tid = threadIdx.x;
    float* row = qkv + (size_t)t * QKV_N;

    if (tid < 64) {
        float pos = (float)positions[t];
        float inv = powf(1.0e6f, -(float)tid * (1.0f / 64.0f));
        float fr = pos * inv;
        float s, c;
        sincosf(fr, &s, &c);
        cs[tid] = c; sn[tid] = s;
    }
    __syncthreads();

    for (int idx = tid; idx < 40 * 64; idx += 256) {
        int head = idx >> 6;
        int i = idx & 63;
        int base = (head < NH) ? head * HD : K_OFF + (head - NH) * HD;
        float c = cs[i], s = sn[i];
        float x1 = row[base + i];
        float x2 = row[base + i + 64];
        row[base + i]      = x1 * c - x2 * s;
        row[base + i + 64] = x2 * c + x1 * s;
    }
    for (int idx = tid; idx < NKH * VDIM; idx += 256) {
        row[V_OFF + idx] *= V_SCALE_C;
    }
}

// =====================================================================
// Prepack K: split each K row into interleaved (hi,lo) bf16 pairs.
// idx over kh x key x 32 uint4-chunks.
// =====================================================================
__global__ __launch_bounds__(256) void prepack_k_kernel(
    const float* __restrict__ qkv)
{
    int idx = blockIdx.x * 256 + threadIdx.x;      // 8*2048*32 = 524288
    int c  = idx & 31;
    int t  = (idx >> 5) & 2047;
    int kh = idx >> 16;
    float4 v = *(const float4*)(qkv + (size_t)t * QKV_N + K_OFF + kh * HD + c * 4);
    u32 h01, l01, h23, l23;
    split2(v.x, v.y, h01, l01);
    split2(v.z, v.w, h23, l23);
    g_kp[((kh << 11) + t) * 32 + c] = make_uint4(h01, l01, h23, l23);
}

// =====================================================================
// Prepack V: transpose to key-pair-major, split hi/lo.
// thread handles 4 n-values of one (kh, keypair).
// =====================================================================
__global__ __launch_bounds__(256) void prepack_v_kernel(
    const float* __restrict__ qkv)
{
    int idx = blockIdx.x * 256 + threadIdx.x;      // 8*1024*16 = 131072
    int c  = idx & 15;                              // n chunk (4 n's)
    int kp = (idx >> 4) & 1023;
    int kh = idx >> 14;
    const float* r0 = qkv + (size_t)(2*kp)     * QKV_N + V_OFF + kh * VDIM + c * 4;
    const float* r1 = qkv + (size_t)(2*kp + 1) * QKV_N + V_OFF + kh * VDIM + c * 4;
    float4 a = *(const float4*)r0;
    float4 b = *(const float4*)r1;
    u32 h0, l0, h1, l1, h2, l2, h3, l3;
    split2(a.x, b.x, h0, l0);
    split2(a.y, b.y, h1, l1);
    split2(a.z, b.z, h2, l2);
    split2(a.w, b.w, h3, l3);
    size_t base = (((size_t)(kh << 10) + kp) * 2) * 16;
    g_vt[base + c]      = make_uint4(h0, h1, h2, h3);
    g_vt[base + 16 + c] = make_uint4(l0, l1, l2, l3);
}

// =====================================================================
// Flash attention: cp.async double-buffered prepacked K/V tiles.
//   S  = QK^T : 3-pass split-bf16 (Q frags in regs, K (hi,lo) in smem)
//   PV        : 3-pass split-bf16 (P packed from regs, V (hi,lo) in smem)
// Block = (head, 64 q rows), 4 warps x 16 rows.
// =====================================================================
#define A_BM 64
#define KP2_STRIDE 136     // u32; interleaved (hi,lo) pairs per key row
#define VT_STRIDE  72      // u32
#define KSTG (64*KP2_STRIDE)                 // 8704 u32
#define VSTG (2*32*VT_STRIDE)                // 4608 u32
#define STG  (KSTG + VSTG)                   // 13312 u32 per stage
#define ATTN_SMEM (2 * STG * 4)              // 104 KB

__global__ __launch_bounds__(128) void attn_kernel(
    const float* __restrict__ qkv, const float* __restrict__ sink,
    float* __restrict__ out)
{
    extern __shared__ u32 smem_a[];

    const int h  = blockIdx.y;
    const int m0 = blockIdx.x * A_BM;
    const int kh = h >> 2;

    const int tid  = threadIdx.x;
    const int warp = tid >> 5;
    const int lane = tid & 31;
    const int g  = lane >> 2;
    const int tg = lane & 3;
    const int wm = warp * 16;

    // ---- Q fragments -> registers (split bf16 hi/lo), once per block ----
    u32 qhi[8][4], qlo[8][4];
    {
        const float* Qr0 = qkv + (size_t)(m0 + wm + g) * QKV_N + h * HD;
        const float* Qr1 = Qr0 + 8 * (size_t)QKV_N;
        #pragma unroll
        for (int ks = 0; ks < 8; ks++) {
            int c0 = ks * 16 + 2 * tg;
            float2 x0 = *(const float2*)(Qr0 + c0);
            float2 x1 = *(const float2*)(Qr1 + c0);
            float2 x2 = *(const float2*)(Qr0 + c0 + 8);
            float2 x3 = *(const float2*)(Qr1 + c0 + 8);
            split2(x0.x, x0.y, qhi[ks][0], qlo[ks][0]);
            split2(x1.x, x1.y, qhi[ks][1], qlo[ks][1]);
            split2(x2.x, x2.y, qhi[ks][2], qlo[ks][2]);
            split2(x3.x, x3.y, qhi[ks][3], qlo[ks][3]);
        }
    }

    const float snk = sink[h];
    float m_r[2] = {snk, snk};
    float l_r[2] = {1.0f, 1.0f};
    float O[8][4];
    #pragma unroll
    for (int nt = 0; nt < 8; nt++)
        #pragma unroll
        for (int r = 0; r < 4; r++) O[nt][r] = 0.f;

    const int gi0 = m0 + wm + g;
    const int gi1 = gi0 + 8;

    int n0s = m0 - WINDOW_SZ;
    if (n0s < 0) n0s = 0;
    const int ntiles = (m0 - n0s) / 64 + 1;

    const uint4* Kp = g_kp + ((size_t)kh << 11) * 32;   // [key][32]
    const uint4* Vp = g_vt + (((size_t)kh << 10) * 2) * 16; // [kp][2][16]

    // ---- issue tile `it` into stage buffer ----
    auto issue_tile = [&](int it) {
        int n0 = n0s + it * 64;
        u32* stg = smem_a + (it & 1) * STG;
        u32* KPb   = stg;
        u32* VThib = stg + KSTG;
        u32* VTlob = VThib + 32 * VT_STRIDE;
        // K: 2048 chunks of 16B
        #pragma unroll
        for (int p = 0; p < 16; p++) {
            int id = tid + p * 128;
            int r = id >> 5, c = id & 31;
            cp16(&KPb[r * KP2_STRIDE + 4*c], &Kp[(n0 + r) * 32 + c]);
        }
        // V: 1024 chunks of 16B
        int kp0 = n0 >> 1;
        #pragma unroll
        for (int p = 0; p < 8; p++) {
            int id = tid + p * 128;
            int kp = id >> 5, hl = (id >> 4) & 1, c = id & 15;
            u32* dst = (hl ? VTlob : VThib) + kp * VT_STRIDE + 4*c;
            cp16(dst, &Vp[((kp0 + kp) * 2 + hl) * 16 + c]);
        }
        CP_COMMIT();
    };

    issue_tile(0);

    for (int it = 0; it < ntiles; it++) {
        const int n0 = n0s + it * 64;
        if (it + 1 < ntiles) {
            issue_tile(it + 1);
            CP_WAIT(1);
        } else {
            CP_WAIT(0);
        }
        __syncthreads();

        u32* stg = smem_a + (it & 1) * STG;
        const u32* KP   = stg;
        const u32* VThi = stg + KSTG;
        const u32* VTlo = VThi + 32 * VT_STRIDE;

        // ---- S = Q K^T (hi*hi + lo*hi + hi*lo) ----
        float Sa[8][4];
        #pragma unroll
        for (int nt = 0; nt < 8; nt++)
            #pragma unroll
            for (int r = 0; r < 4; r++) Sa[nt][r] = 0.f;

        #pragma unroll
        for (int ks = 0; ks < 8; ks++) {
            #pragma unroll
            for (int nt = 0; nt < 8; nt++) {
                int base = (nt*8 + g) * KP2_STRIDE + 2*(ks*8 + tg);
                uint2 b0 = *(const uint2*)&KP[base];
                uint2 b1 = *(const uint2*)&KP[base + 8];
                u32 bh[2] = {b0.x, b1.x};
                u32 bl[2] = {b0.y, b1.y};
                mma_bf16(Sa[nt], qhi[ks], bh);
                mma_bf16(Sa[nt], qlo[ks], bh);
                mma_bf16(Sa[nt], qhi[ks], bl);
            }
        }

        // ---- scale + mask ----
        #pragma unroll
        for (int nt = 0; nt < 8; nt++) {
            #pragma unroll
            for (int cc = 0; cc < 2; cc++) {
                int gj = n0 + nt*8 + 2*tg + cc;
                bool v0 = (gj <= gi0) && (gj + WINDOW_SZ > gi0);
                bool v1 = (gj <= gi1) && (gj + WINDOW_SZ > gi1);
                Sa[nt][cc]     = v0 ? Sa[nt][cc]     * SCALE_ATTN : -1.0e30f;
                Sa[nt][2 + cc] = v1 ? Sa[nt][2 + cc] * SCALE_ATTN : -1.0e30f;
            }
        }

        // ---- online softmax ----
        float tm0 = -1.0e30f, tm1 = -1.0e30f;
        #pragma unroll
        for (int nt = 0; nt < 8; nt++) {
            tm0 = fmaxf(tm0, fmaxf(Sa[nt][0], Sa[nt][1]));
            tm1 = fmaxf(tm1, fmaxf(Sa[nt][2], Sa[nt][3]));
        }
        tm0 = fmaxf(tm0, __shfl_xor_sync(0xffffffffu, tm0, 1));
        tm0 = fmaxf(tm0, __shfl_xor_sync(0xffffffffu, tm0, 2));
        tm1 = fmaxf(tm1, __shfl_xor_sync(0xffffffffu, tm1, 1));
        tm1 = fmaxf(tm1, __shfl_xor_sync(0xffffffffu, tm1, 2));

        float mn0 = fmaxf(m_r[0], tm0);
        float mn1 = fmaxf(m_r[1], tm1);
        float corr0 = __expf(m_r[0] - mn0);
        float corr1 = __expf(m_r[1] - mn1);
        m_r[0] = mn0; m_r[1] = mn1;

        float rs0 = 0.f, rs1 = 0.f;
        #pragma unroll
        for (int nt = 0; nt < 8; nt++) {
            #pragma unroll
            for (int cc = 0; cc < 2; cc++) {
                float p0 = __expf(Sa[nt][cc]     - mn0);
                float p1 = __expf(Sa[nt][2 + cc] - mn1);
                Sa[nt][cc]     = p0;
                Sa[nt][2 + cc] = p1;
                rs0 += p0; rs1 += p1;
            }
        }
        rs0 += __shfl_xor_sync(0xffffffffu, rs0, 1);
        rs0 += __shfl_xor_sync(0xffffffffu, rs0, 2);
        rs1 += __shfl_xor_sync(0xffffffffu, rs1, 1);
        rs1 += __shfl_xor_sync(0xffffffffu, rs1, 2);

        l_r[0] = l_r[0] * corr0 + rs0;
        l_r[1] = l_r[1] * corr1 + rs1;
        #pragma unroll
        for (int nt = 0; nt < 8; nt++) {
            O[nt][0] *= corr0; O[nt][1] *= corr0;
            O[nt][2] *= corr1; O[nt][3] *= corr1;
        }

        // ---- O += P V : P packed from registers, V (hi,lo) in smem ----
        #pragma unroll
        for (int kq = 0; kq < 4; kq++) {
            u32 phi[4], plo[4];
            split2(Sa[2*kq][0],   Sa[2*kq][1],   phi[0], plo[0]);
            split2(Sa[2*kq][2],   Sa[2*kq][3],   phi[1], plo[1]);
            split2(Sa[2*kq+1][0], Sa[2*kq+1][1], phi[2], plo[2]);
            split2(Sa[2*kq+1][2], Sa[2*kq+1][3], phi[3], plo[3]);
            #pragma unroll
            for (int nt = 0; nt < 8; nt++) {
                int i0 = (kq*8 + tg) * VT_STRIDE + nt*8 + g;
                u32 vh[2], vl[2];
                vh[0] = VThi[i0];                 vl[0] = VTlo[i0];
                vh[1] = VThi[i0 + 4*VT_STRIDE];   vl[1] = VTlo[i0 + 4*VT_STRIDE];
                mma_bf16(O[nt], phi, vh);
                mma_bf16(O[nt], plo, vh);
                mma_bf16(O[nt], phi, vl);
            }
        }
        __syncthreads();   // stage fully consumed before it is refilled
    }

    // ---- epilogue ----
    float inv0 = 1.0f / l_r[0];
    float inv1 = 1.0f / l_r[1];
    #pragma unroll
    for (int nt = 0; nt < 8; nt++) {
        int col = h * VDIM + nt*8 + 2*tg;
        *(float2*)(out + (size_t)gi0 * (NH * VDIM) + col) =
            make_float2(O[nt][0] * inv0, O[nt][1] * inv0);
        *(float2*)(out + (size_t)gi1 * (NH * VDIM) + col) =
            make_float2(O[nt][2] * inv1, O[nt][3] * inv1);
    }
}

// =====================================================================
// launch
// =====================================================================
extern "C" void kernel_launch(void* const* d_in, const int* in_sizes, int n_in,
                              void* d_out, int out_size)
{
    const int*   positions = (const int*)  d_in[0];
    const float* hidden    = (const float*)d_in[1];
    const float* Wqkv      = (const float*)d_in[2];
    const float* Wo        = (const float*)d_in[3];
    const float* sink      = (const float*)d_in[4];
    float* out = (float*)d_out;

    float *qkv, *attn;
    cudaGetSymbolAddress((void**)&qkv,  g_qkv);
    cudaGetSymbolAddress((void**)&attn, g_attn);

    cudaFuncSetAttribute(gemm_tf32_kernel,
                         cudaFuncAttributeMaxDynamicSharedMemorySize, GEMM_SMEM);
    cudaFuncSetAttribute(attn_kernel,
                         cudaFuncAttributeMaxDynamicSharedMemorySize, ATTN_SMEM);

    // 1) QKV projection (tf32 tensor cores)
    {
        dim3 grid(QKV_N / GBN, T_TOK / GBM);
        gemm_tf32_kernel<<<grid, 256, GEMM_SMEM>>>(hidden, Wqkv, qkv,
                                                   T_TOK, QKV_N, HID);
    }
    // 2) RoPE + V scale
    rope_kernel<<<T_TOK, 256>>>(qkv, positions);
    // 3) prepack K and V into bf16 hi/lo layouts
    prepack_k_kernel<<<2048, 256>>>(qkv);
    prepack_v_kernel<<<512, 256>>>(qkv);
    // 4) attention (cp.async pipelined, split-bf16)
    {
        dim3 grid(T_TOK / A_BM, NH);
        attn_kernel<<<grid, 128, ATTN_SMEM>>>(qkv, sink, attn);
    }
    // 5) output projection (tf32 tensor cores)
    {
        dim3 grid(HID / GBN, T_TOK / GBM);
        gemm_tf32_kernel<<<grid, 256, GEMM_SMEM>>>(attn, Wo, out,
                                                   T_TOK, HID, NH * VDIM);
    }
}